// round 13
// baseline (speedup 1.0000x reference)
#include <cuda_runtime.h>
#include <cuda_fp16.h>
#include <cstdint>

// Problem constants
#define MB 16384
#define SS 1024
#define LL 256
#define KK 4096
#define HH 64

#define BK 32
#define PAD 4

// table kernel keeps the K'=192 concat layout (12 k16 tiles)
#define KT_TOT 12

// enc1 mma kernel
#define E_BM 64
#define E_NCH 16

// ---- scratch ----
static __device__ float4 g_w1p[16384];               // 256 KB W1 fp16 frags
static __device__ float4 g_dw2p[64 * KT_TOT * 32];   // 384 KB dw2 fp16 frags (concat)
static __device__ float4 g_ap[1024 * 8 * 32];        // 4.2 MB A frags [mtile][kt8: 4h+4l][lane]
static __device__ float4 g_bp[256 * 8 * 32];         // 1.0 MB B frags [np][kt8: 4h+4l][lane]
static __device__ float g_G[(size_t)KK * HH];
static __device__ float g_w2t[(size_t)LL * HH];
static __device__ float g_table[(size_t)KK * SS];
static __device__ float g_c[KK];                     // ||w||^2 - 2 b2.w
static __device__ unsigned long long g_key[MB];

// ============================ helpers ======================================
__device__ __forceinline__ uint32_t smem_u32(const void* p) {
    uint32_t a;
    asm("{ .reg .u64 t; cvta.to.shared.u64 t, %1; cvt.u32.u64 %0, t; }"
        : "=r"(a) : "l"(p));
    return a;
}
__device__ __forceinline__ unsigned int f2s(float f) {
    unsigned int u = __float_as_uint(f);
    return (u & 0x80000000u) ? ~u : (u | 0x80000000u);
}
__device__ __forceinline__ void mma16(float c[4], const float4& a, float b0, float b1) {
    asm volatile(
        "mma.sync.aligned.m16n8k16.row.col.f32.f16.f16.f32 "
        "{%0,%1,%2,%3}, {%4,%5,%6,%7}, {%8,%9}, {%0,%1,%2,%3};"
        : "+f"(c[0]), "+f"(c[1]), "+f"(c[2]), "+f"(c[3])
        : "r"(__float_as_uint(a.x)), "r"(__float_as_uint(a.y)),
          "r"(__float_as_uint(a.z)), "r"(__float_as_uint(a.w)),
          "r"(__float_as_uint(b0)), "r"(__float_as_uint(b1)));
}
__device__ __forceinline__ uint32_t h2pack(float lo, float hi) {
    __half2 h = __halves2half2(__float2half_rn(lo), __float2half_rn(hi));
    return *(uint32_t*)&h;
}
__device__ __forceinline__ void split2(float a, float b, uint32_t& hi, uint32_t& lo) {
    float ha = __half2float(__float2half_rn(a));
    float hb = __half2float(__float2half_rn(b));
    hi = h2pack(a, b);
    lo = h2pack(a - ha, b - hb);
}
#define CP_ASYNC16(dst, src) \
    asm volatile("cp.async.cg.shared.global [%0], [%1], 16;" \
                 :: "r"(dst), "l"(src))
#define CP_COMMIT() asm volatile("cp.async.commit_group;" ::: "memory")
#define CP_WAIT2()  asm volatile("cp.async.wait_group 2;" ::: "memory")
#define CP_WAIT0()  asm volatile("cp.async.wait_group 0;" ::: "memory")

// ============================ prep kernel (merged) ==========================
__global__ void k_prep(const float* __restrict__ emb, const float* __restrict__ b2,
                       const float* __restrict__ w2, float* __restrict__ w2t,
                       const float* __restrict__ dw2, float4* __restrict__ Dp,
                       const float* __restrict__ W1, float4* __restrict__ Wp) {
    int b = blockIdx.x, t = threadIdx.x;
    if (b < 64) {
        g_key[b * 256 + t] = 0xFFFFFFFFFFFFFFFFull;
    } else if (b < 80) {
        int r = (b - 64) * 256 + t;
        const float4* p = (const float4*)(emb + (size_t)r * LL);
        const float4* q = (const float4*)b2;
        float s = 0.f, u = 0.f;
#pragma unroll
        for (int i = 0; i < LL / 4; i++) {
            float4 v = p[i], w = q[i];
            s += v.x * v.x + v.y * v.y + v.z * v.z + v.w * v.w;
            u += v.x * w.x + v.y * w.y + v.z * w.z + v.w * w.w;
        }
        g_c[r] = s - 2.0f * u;
    } else if (b < 144) {
        int idx = (b - 80) * 256 + t;
        int l = idx >> 6, j = idx & 63;
        w2t[l * 64 + j] = w2[j * 256 + l];
    } else if (b < 240) {
        int idx = (b - 144) * 256 + t;
        int np = idx / 384;
        int rem = idx % 384;
        int kt = rem >> 5, lane = rem & 31;
        int n0 = np * 16 + (lane >> 2);
        int kb = kt * 16 + 2 * (lane & 3);
        float4 o;
#pragma unroll
        for (int e = 0; e < 4; e++) {
            int n = n0 + (e >> 1) * 8;
            int kp = kb + (e & 1) * 8;
            int k = (kp < 64) ? kp : (kp < 128 ? kp - 64 : kp - 128);
            bool is_lo = (kp >= 64 && kp < 128);
            float v0 = dw2[(size_t)k * 1024 + n];
            float v1 = dw2[(size_t)(k + 1) * 1024 + n];
            uint32_t h, l;
            split2(v0, v1, h, l);
            ((float*)&o)[e] = __uint_as_float(is_lo ? l : h);
        }
        Dp[idx] = o;
    } else {
        int idx = (b - 240) * 256 + t;
        int g = idx >> 11, ktg = (idx >> 5) & 63, lane = idx & 31;
        int n = g * 8 + (lane >> 2);
        int kb = ktg * 16 + 2 * (lane & 3);
        float4 o;
        uint32_t h0, l0, h1, l1;
        split2(W1[(size_t)kb * 64 + n],       W1[(size_t)(kb + 1) * 64 + n], h0, l0);
        split2(W1[(size_t)(kb + 8) * 64 + n], W1[(size_t)(kb + 9) * 64 + n], h1, l1);
        o.x = __uint_as_float(h0);
        o.y = __uint_as_float(h1);
        o.z = __uint_as_float(l0);
        o.w = __uint_as_float(l1);
        Wp[idx] = o;
    }
}

// ============================ enc1 fp16 tensor-core GEMM ====================
__global__ __launch_bounds__(256) void k_enc1_mma(
    const float* __restrict__ X, const float4* __restrict__ Wp,
    const float* __restrict__ bias, float4* __restrict__ Ap) {
    extern __shared__ char smraw[];
    float* xs = (float*)smraw;                  // 3 x [64][68] floats
    float4* ws = (float4*)(smraw + 52224);      // 3 x 1024 float4
    const uint32_t sb = smem_u32(smraw);
    const int tid = threadIdx.x, warp = tid >> 5, lane = tid & 31;
    const int wm = warp >> 1, wn = warp & 1;
    const int m0 = blockIdx.x * E_BM;
    float acc[4][4] = {};

    auto stage = [&](int c) {
        const int buf = c % 3;
        const uint32_t xb = sb + (uint32_t)buf * 17408u;
        const uint32_t wb = sb + 52224u + (uint32_t)buf * 16384u;
#pragma unroll
        for (int i = 0; i < 4; i++) {
            int s = i * 256 + tid;
            int row = s >> 4, q = s & 15;
            const float* src = X + (size_t)(m0 + row) * 1024 + c * 64 + q * 4;
            CP_ASYNC16(xb + (uint32_t)(row * 272 + q * 16), src);
        }
#pragma unroll
        for (int i = 0; i < 4; i++) {
            int s = i * 256 + tid;
            int g = s >> 7, ktl = (s >> 5) & 3, ln = s & 31;
            const float4* src = Wp + ((size_t)g * 64 + c * 4 + ktl) * 32 + ln;
            CP_ASYNC16(wb + (uint32_t)s * 16u, src);
        }
    };
    stage(0); CP_COMMIT();
    stage(1); CP_COMMIT();

    const int r = lane >> 2, cc = lane & 3;
    for (int c = 0; c < E_NCH; c++) {
        if (c + 2 < E_NCH) stage(c + 2);
        CP_COMMIT();
        CP_WAIT2();
        __syncthreads();
        const float* xc = xs + (c % 3) * 4352;
        const float4* wc = ws + (c % 3) * 1024;
#pragma unroll
        for (int kt = 0; kt < 4; kt++) {
            float4 bw[4];
#pragma unroll
            for (int nf = 0; nf < 4; nf++)
                bw[nf] = wc[(wn * 4 + nf) * 128 + kt * 32 + lane];
            const float* xp = xc + (size_t)(wm * 16) * 68 + kt * 16;
            float2 u0 = *(const float2*)(xp + r * 68 + 2 * cc);
            float2 u1 = *(const float2*)(xp + (r + 8) * 68 + 2 * cc);
            float2 u2 = *(const float2*)(xp + r * 68 + 2 * cc + 8);
            float2 u3 = *(const float2*)(xp + (r + 8) * 68 + 2 * cc + 8);
            float4 ah, al;
            uint32_t h, l;
            split2(u0.x, u0.y, h, l); ah.x = __uint_as_float(h); al.x = __uint_as_float(l);
            split2(u1.x, u1.y, h, l); ah.y = __uint_as_float(h); al.y = __uint_as_float(l);
            split2(u2.x, u2.y, h, l); ah.z = __uint_as_float(h); al.z = __uint_as_float(l);
            split2(u3.x, u3.y, h, l); ah.w = __uint_as_float(h); al.w = __uint_as_float(l);
#pragma unroll
            for (int nf = 0; nf < 4; nf++) {
                mma16(acc[nf], ah, bw[nf].x, bw[nf].y);
                mma16(acc[nf], ah, bw[nf].z, bw[nf].w);
                mma16(acc[nf], al, bw[nf].x, bw[nf].y);
            }
        }
        __syncthreads();
    }
    CP_WAIT0();

    {
        const int mtile = blockIdx.x * 4 + wm;
#pragma unroll
        for (int p = 0; p < 2; p++) {
            const int cb = wn * 32 + p * 16 + 2 * cc;
            float b0 = bias[cb],     b1v = bias[cb + 1];
            float b2 = bias[cb + 8], b3v = bias[cb + 9];
            float v0 = fmaxf(acc[2 * p][0] + b0,  0.f);
            float v1 = fmaxf(acc[2 * p][1] + b1v, 0.f);
            float v2 = fmaxf(acc[2 * p][2] + b0,  0.f);
            float v3 = fmaxf(acc[2 * p][3] + b1v, 0.f);
            float w0 = fmaxf(acc[2 * p + 1][0] + b2,  0.f);
            float w1 = fmaxf(acc[2 * p + 1][1] + b3v, 0.f);
            float w2 = fmaxf(acc[2 * p + 1][2] + b2,  0.f);
            float w3 = fmaxf(acc[2 * p + 1][3] + b3v, 0.f);
            float4 hf, lf;
            uint32_t h, l;
            split2(v0, v1, h, l); hf.x = __uint_as_float(h); lf.x = __uint_as_float(l);
            split2(v2, v3, h, l); hf.y = __uint_as_float(h); lf.y = __uint_as_float(l);
            split2(w0, w1, h, l); hf.z = __uint_as_float(h); lf.z = __uint_as_float(l);
            split2(w2, w3, h, l); hf.w = __uint_as_float(h); lf.w = __uint_as_float(l);
            const int kt = wn * 2 + p;
            Ap[((size_t)mtile * 8 + kt) * 32 + lane]     = hf;
            Ap[((size_t)mtile * 8 + kt + 4) * 32 + lane] = lf;
        }
    }
}

// ============================ dual P/G GEMM + B' emission ===================
__global__ __launch_bounds__(256) void k_dual(
    const float* __restrict__ emb, const float* __restrict__ Wp,
    const float* __restrict__ Wg, const float* __restrict__ bg,
    float* __restrict__ G, float4* __restrict__ Bp) {
    __shared__ float a_s[BK][32 + PAD];
    __shared__ float wp_s[BK][64 + PAD];
    __shared__ float wg_s[BK][64 + PAD];
    __shared__ float s_P[32][68];
    int tid = threadIdx.x;
    int tx = tid & 15, ty = tid >> 4;
    int m0 = blockIdx.x * 32;
    float accp[2][4] = {}, accg[2][4] = {};

    for (int k0 = 0; k0 < LL; k0 += BK) {
        {
            int row = tid >> 3, kq = tid & 7;
            float4 v = *(const float4*)(emb + (size_t)(m0 + row) * LL + k0 + kq * 4);
            a_s[kq * 4 + 0][row] = v.x; a_s[kq * 4 + 1][row] = v.y;
            a_s[kq * 4 + 2][row] = v.z; a_s[kq * 4 + 3][row] = v.w;
        }
#pragma unroll
        for (int i = 0; i < 2; i++) {
            int f4 = tid + i * 256;
            int kr = f4 >> 4, nq = f4 & 15;
            float4 vp = *(const float4*)(Wp + (size_t)(k0 + kr) * 64 + nq * 4);
            wp_s[kr][nq * 4 + 0] = vp.x; wp_s[kr][nq * 4 + 1] = vp.y;
            wp_s[kr][nq * 4 + 2] = vp.z; wp_s[kr][nq * 4 + 3] = vp.w;
            float4 vg = *(const float4*)(Wg + (size_t)(k0 + kr) * 64 + nq * 4);
            wg_s[kr][nq * 4 + 0] = vg.x; wg_s[kr][nq * 4 + 1] = vg.y;
            wg_s[kr][nq * 4 + 2] = vg.z; wg_s[kr][nq * 4 + 3] = vg.w;
        }
        __syncthreads();
#pragma unroll
        for (int k = 0; k < BK; k++) {
            float a0 = a_s[k][ty * 2], a1 = a_s[k][ty * 2 + 1];
            float bp[4], bgv[4];
            *(float4*)bp  = *(float4*)&wp_s[k][tx * 4];
            *(float4*)bgv = *(float4*)&wg_s[k][tx * 4];
#pragma unroll
            for (int j = 0; j < 4; j++) {
                accp[0][j] += a0 * bp[j];  accp[1][j] += a1 * bp[j];
                accg[0][j] += a0 * bgv[j]; accg[1][j] += a1 * bgv[j];
            }
        }
        __syncthreads();
    }
    float4 bv = *(const float4*)(bg + tx * 4);
#pragma unroll
    for (int i = 0; i < 2; i++) {
        int m = m0 + ty * 2 + i;
        float4 vg;
        vg.x = fmaxf(accg[i][0] + bv.x, 0.f);
        vg.y = fmaxf(accg[i][1] + bv.y, 0.f);
        vg.z = fmaxf(accg[i][2] + bv.z, 0.f);
        vg.w = fmaxf(accg[i][3] + bv.w, 0.f);
        *(float4*)(G + (size_t)m * 64 + tx * 4) = vg;
        *(float4*)&s_P[ty * 2 + i][tx * 4] = *(float4*)accp[i];
    }
    __syncthreads();

#pragma unroll
    for (int j = 0; j < 2; j++) {
        int idx = j * 256 + tid;
        int nt = idx >> 8;
        int rem = idx & 255;
        int kt = rem >> 5, lane = rem & 31;
        int nl = nt * 16 + (lane >> 2);
        int kb = (kt & 3) * 16 + 2 * (lane & 3);
        bool is_lo = (kt >= 4);
        float4 o;
#pragma unroll
        for (int e = 0; e < 4; e++) {
            int n = nl + (e >> 1) * 8;
            int k = kb + (e & 1) * 8;
            uint32_t h, l;
            split2(s_P[n][k], s_P[n][k + 1], h, l);
            ((float*)&o)[e] = __uint_as_float(is_lo ? l : h);
        }
        Bp[((size_t)(blockIdx.x * 2 + nt) * 8 + kt) * 32 + lane] = o;
    }
}

// ============================ table fp16 mma GEMM ===========================
__global__ __launch_bounds__(256) void k_table_mma(
    const float* __restrict__ G, const float4* __restrict__ Dp,
    const float* __restrict__ bias, float* __restrict__ T) {
    extern __shared__ char tsm[];
    float* a_s = (float*)tsm;                      // [128][68] fp32 G tile
    float4* bs = (float4*)(tsm + 34816);           // 3072 float4 B' frags
    const uint32_t sb = smem_u32(tsm);
    const int tid = threadIdx.x, warp = tid >> 5, lane = tid & 31;
    const int wm = warp >> 1, wn = warp & 1;
    const int n0 = blockIdx.x * 128, m0 = blockIdx.y * 128;

#pragma unroll
    for (int i = 0; i < 8; i++) {
        int s = i * 256 + tid;
        int row = s >> 4, q = s & 15;
        CP_ASYNC16(sb + (uint32_t)(row * 272 + q * 16),
                   G + (size_t)(m0 + row) * 64 + q * 4);
    }
    const float4* dsrc = Dp + (size_t)(n0 >> 4) * 384;
#pragma unroll
    for (int i = 0; i < 12; i++) {
        int s = i * 256 + tid;
        CP_ASYNC16(sb + 34816u + (uint32_t)s * 16u, dsrc + s);
    }
    CP_COMMIT();
    CP_WAIT0();
    __syncthreads();

    const int r = lane >> 2, cc = lane & 3;
    float acc[2][8][4] = {};
#pragma unroll
    for (int kpos = 0; kpos < 4; kpos++) {
        float4 ah[2], al[2];
#pragma unroll
        for (int mf = 0; mf < 2; mf++) {
            const float* xp = a_s + (size_t)(wm * 32 + mf * 16) * 68 + kpos * 16;
            float2 u0 = *(const float2*)(xp + r * 68 + 2 * cc);
            float2 u1 = *(const float2*)(xp + (r + 8) * 68 + 2 * cc);
            float2 u2 = *(const float2*)(xp + r * 68 + 2 * cc + 8);
            float2 u3 = *(const float2*)(xp + (r + 8) * 68 + 2 * cc + 8);
            uint32_t h, l;
            split2(u0.x, u0.y, h, l); ah[mf].x = __uint_as_float(h); al[mf].x = __uint_as_float(l);
            split2(u1.x, u1.y, h, l); ah[mf].y = __uint_as_float(h); al[mf].y = __uint_as_float(l);
            split2(u2.x, u2.y, h, l); ah[mf].z = __uint_as_float(h); al[mf].z = __uint_as_float(l);
            split2(u3.x, u3.y, h, l); ah[mf].w = __uint_as_float(h); al[mf].w = __uint_as_float(l);
        }
#pragma unroll
        for (int term = 0; term < 3; term++) {
            const int kt = kpos + term * 4;
#pragma unroll
            for (int npl = 0; npl < 4; npl++) {
                float4 bf = bs[((wn * 4 + npl) * KT_TOT + kt) * 32 + lane];
#pragma unroll
                for (int mf = 0; mf < 2; mf++) {
                    const float4& aa = (term == 2) ? al[mf] : ah[mf];
                    mma16(acc[mf][npl * 2],     aa, bf.x, bf.y);
                    mma16(acc[mf][npl * 2 + 1], aa, bf.z, bf.w);
                }
            }
        }
    }

#pragma unroll
    for (int mf = 0; mf < 2; mf++) {
        int row0 = m0 + wm * 32 + mf * 16 + r;
#pragma unroll
        for (int nf = 0; nf < 8; nf++) {
            int n = n0 + wn * 64 + nf * 8 + 2 * cc;
            float b0 = bias[n], b1v = bias[n + 1];
            float2 v0, v1;
            v0.x = acc[mf][nf][0] + b0;  v0.y = acc[mf][nf][1] + b1v;
            v1.x = acc[mf][nf][2] + b0;  v1.y = acc[mf][nf][3] + b1v;
            *(float2*)(T + (size_t)row0 * 1024 + n)       = v0;
            *(float2*)(T + (size_t)(row0 + 8) * 1024 + n) = v1;
        }
    }
}

// ============================ fp16 mma distance kernel ======================
// 128m x 256n per CTA, two 128x128 subtiles reusing A. hi/lo K=64 layout.
// Cheap argmin: fp32 running (bestd, bestc) across subtiles, single pack+atomic.
__global__ __launch_bounds__(256, 2) void k_dist_mma(
    const float4* __restrict__ Ap, const float4* __restrict__ Bp) {
    extern __shared__ float4 sm[];
    __shared__ unsigned long long s_key[128];
    __shared__ float s_c[256];

    const int tid = threadIdx.x;
    const int warp = tid >> 5, lane = tid & 31;
    const int wm = warp >> 2, wn = warp & 3;     // warp tile 64m x 32n
    const int mt0 = blockIdx.y * 8;
    const int m0 = blockIdx.y * 128, n0 = blockIdx.x * 256;

    if (tid < 128) s_key[tid] = 0xFFFFFFFFFFFFFFFFull;
    s_c[tid] = g_c[n0 + tid];

    const uint32_t sb = smem_u32(sm);
    {
        const float4* ga = Ap + (size_t)mt0 * 256;
#pragma unroll
        for (int i = 0; i < 8; i++) {
            int s = i * 256 + tid;
            CP_ASYNC16(sb + (uint32_t)s * 16u, ga + s);
        }
        const float4* gb = Bp + (size_t)blockIdx.x * 4096;
#pragma unroll
        for (int i = 0; i < 16; i++) {
            int s = i * 256 + tid;
            CP_ASYNC16(sb + 32768u + (uint32_t)s * 16u, gb + s);
        }
    }
    CP_COMMIT();
    CP_WAIT0();
    __syncthreads();

    float bestd[4][2];
    int bestc[4][2];
#pragma unroll
    for (int mf = 0; mf < 4; mf++)
#pragma unroll
        for (int half = 0; half < 2; half++) {
            bestd[mf][half] = __int_as_float(0x7f800000);  // +inf
            bestc[mf][half] = 0;
        }

    const float4* SA = sm;
#pragma unroll
    for (int j = 0; j < 2; j++) {
        const float4* SB = sm + 2048 + j * 2048;
        float acc[4][4][4] = {};
#pragma unroll
        for (int kt = 0; kt < 4; kt++) {
            float4 bh[2], bl[2];
#pragma unroll
            for (int p = 0; p < 2; p++) {
                bh[p] = SB[((wn * 2 + p) * 8 + kt) * 32 + lane];
                bl[p] = SB[((wn * 2 + p) * 8 + kt + 4) * 32 + lane];
            }
#pragma unroll
            for (int mf = 0; mf < 4; mf++) {
                float4 ah = SA[((wm * 4 + mf) * 8 + kt) * 32 + lane];
                float4 al = SA[((wm * 4 + mf) * 8 + kt + 4) * 32 + lane];
#pragma unroll
                for (int p = 0; p < 2; p++) {
                    mma16(acc[mf][2 * p],     ah, bh[p].x, bh[p].y);
                    mma16(acc[mf][2 * p],     ah, bl[p].x, bl[p].y);
                    mma16(acc[mf][2 * p],     al, bh[p].x, bh[p].y);
                    mma16(acc[mf][2 * p + 1], ah, bh[p].z, bh[p].w);
                    mma16(acc[mf][2 * p + 1], ah, bl[p].z, bl[p].w);
                    mma16(acc[mf][2 * p + 1], al, bh[p].z, bh[p].w);
                }
            }
        }
        // fold subtile j into running (bestd, bestc); cols ascend (nt, then +1),
        // j=0 before j=1, strict '<' => first-index tie-break preserved.
#pragma unroll
        for (int mf = 0; mf < 4; mf++) {
#pragma unroll
            for (int half = 0; half < 2; half++) {
#pragma unroll
                for (int nt = 0; nt < 4; nt++) {
                    int cb = wn * 32 + nt * 8 + 2 * (lane & 3);
                    float d0 = fmaf(-2.0f, acc[mf][nt][half * 2 + 0],
                                    s_c[j * 128 + cb]);
                    float d1 = fmaf(-2.0f, acc[mf][nt][half * 2 + 1],
                                    s_c[j * 128 + cb + 1]);
                    int col = n0 + j * 128 + cb;
                    if (d0 < bestd[mf][half]) {
                        bestd[mf][half] = d0; bestc[mf][half] = col;
                    }
                    if (d1 < bestd[mf][half]) {
                        bestd[mf][half] = d1; bestc[mf][half] = col + 1;
                    }
                }
            }
        }
    }
    // single pack + shared atomic per slot
#pragma unroll
    for (int mf = 0; mf < 4; mf++) {
#pragma unroll
        for (int half = 0; half < 2; half++) {
            int rloc = wm * 64 + mf * 16 + (lane >> 2) + half * 8;
            unsigned long long key =
                ((unsigned long long)f2s(bestd[mf][half]) << 32) |
                (unsigned int)bestc[mf][half];
            atomicMin(&s_key[rloc], key);
        }
    }
    __syncthreads();
    if (tid < 128) atomicMin(&g_key[m0 + tid], s_key[tid]);
}

// ---------------------------------------------------------------------------
__global__ void k_gather(float* __restrict__ out) {
    int b = blockIdx.x * 2 + (threadIdx.x >> 8);
    int q = threadIdx.x & 255;
    unsigned int idx = (unsigned int)(g_key[b] & 0xFFFFFFFFu);
    const float4* src = (const float4*)(g_table + (size_t)idx * SS);
    float4 v = src[q];
    float4* dst = (float4*)(out + (size_t)b * SS) + q;
    asm volatile("st.global.cs.v4.f32 [%0], {%1, %2, %3, %4};"
                 :: "l"(dst), "f"(v.x), "f"(v.y), "f"(v.z), "f"(v.w));
}

// ---------------------------------------------------------------------------
extern "C" void kernel_launch(void* const* d_in, const int* in_sizes, int n_in,
                              void* d_out, int out_size) {
    const float* x    = (const float*)d_in[0];
    const float* ew1  = (const float*)d_in[1];
    const float* eb1  = (const float*)d_in[2];
    const float* ew2  = (const float*)d_in[3];
    const float* eb2  = (const float*)d_in[4];
    const float* emb  = (const float*)d_in[5];
    const float* dw1  = (const float*)d_in[6];
    const float* db1  = (const float*)d_in[7];
    const float* dw2  = (const float*)d_in[8];
    const float* db2  = (const float*)d_in[9];
    float* out = (float*)d_out;

    void *p_w2t, *p_w1p, *p_dw2p, *p_ap, *p_bp, *p_G, *p_table;
    cudaGetSymbolAddress(&p_w2t, g_w2t);
    cudaGetSymbolAddress(&p_w1p, g_w1p);
    cudaGetSymbolAddress(&p_dw2p, g_dw2p);
    cudaGetSymbolAddress(&p_ap, g_ap);
    cudaGetSymbolAddress(&p_bp, g_bp);
    cudaGetSymbolAddress(&p_G, g_G);
    cudaGetSymbolAddress(&p_table, g_table);

    static int smem_set = 0;
    const int DYN_DIST = 98304;
    const int DYN_ENC1 = 101376;
    const int DYN_TAB  = 34816 + 3072 * 16;
    if (!smem_set) {
        cudaFuncSetAttribute(k_dist_mma, cudaFuncAttributeMaxDynamicSharedMemorySize,
                             DYN_DIST);
        cudaFuncSetAttribute(k_enc1_mma, cudaFuncAttributeMaxDynamicSharedMemorySize,
                             DYN_ENC1);
        cudaFuncSetAttribute(k_table_mma, cudaFuncAttributeMaxDynamicSharedMemorySize,
                             DYN_TAB);
        smem_set = 1;
    }

    // 1. prep
    k_prep<<<304, 256>>>(emb, eb2, ew2, (float*)p_w2t, dw2, (float4*)p_dw2p,
                         ew1, (float4*)p_w1p);
    // 2. P/G fused; hi/lo B' frags
    k_dual<<<KK / 32, 256>>>(emb, (const float*)p_w2t, dw1, db1,
                             (float*)p_G, (float4*)p_bp);
    // 3. encoder layer 1 -> hi/lo A' frags
    k_enc1_mma<<<MB / E_BM, 256, DYN_ENC1>>>(x, (const float4*)p_w1p, eb1,
                                             (float4*)p_ap);
    // 4. distances + fused argmin (profiled slot)
    k_dist_mma<<<dim3(KK / 256, MB / 128), 256, DYN_DIST>>>((const float4*)p_ap,
                                                            (const float4*)p_bp);
    // 5. decoder table
    k_table_mma<<<dim3(SS / 128, KK / 128), 256, DYN_TAB>>>(
        (const float*)p_G, (const float4*)p_dw2p, db2, (float*)p_table);
    // 6. decoded output gather
    k_gather<<<MB / 2, 512>>>(out);
}

// round 14
// speedup vs baseline: 1.1495x; 1.1495x over previous
#include <cuda_runtime.h>
#include <cuda_fp16.h>
#include <cstdint>

// Problem constants
#define MB 16384
#define SS 1024
#define LL 256
#define KK 4096
#define HH 64

#define BK 32
#define PAD 4

// table kernel keeps the K'=192 concat layout (12 k16 tiles)
#define KT_TOT 12

// enc1 mma kernel
#define E_BM 64
#define E_NCH 16

// ---- scratch ----
static __device__ float4 g_w1p[16384];               // 256 KB W1 fp16 frags
static __device__ float4 g_dw2p[64 * KT_TOT * 32];   // 384 KB dw2 fp16 frags (concat)
static __device__ float4 g_ap[1024 * 8 * 32];        // 4.2 MB A frags [mtile][kt8: 4h+4l][lane]
static __device__ float4 g_bp[256 * 8 * 32];         // 1.0 MB B frags [np][kt8: 4h+4l][lane]
static __device__ float g_G[(size_t)KK * HH];
static __device__ float g_w2t[(size_t)LL * HH];
static __device__ float g_table[(size_t)KK * SS];
static __device__ float g_c[KK];                     // ||w||^2 - 2 b2.w
static __device__ unsigned long long g_key[MB];

// ============================ helpers ======================================
__device__ __forceinline__ uint32_t smem_u32(const void* p) {
    uint32_t a;
    asm("{ .reg .u64 t; cvta.to.shared.u64 t, %1; cvt.u32.u64 %0, t; }"
        : "=r"(a) : "l"(p));
    return a;
}
__device__ __forceinline__ unsigned int f2s(float f) {
    unsigned int u = __float_as_uint(f);
    return (u & 0x80000000u) ? ~u : (u | 0x80000000u);
}
__device__ __forceinline__ void mma16(float c[4], const float4& a, float b0, float b1) {
    asm volatile(
        "mma.sync.aligned.m16n8k16.row.col.f32.f16.f16.f32 "
        "{%0,%1,%2,%3}, {%4,%5,%6,%7}, {%8,%9}, {%0,%1,%2,%3};"
        : "+f"(c[0]), "+f"(c[1]), "+f"(c[2]), "+f"(c[3])
        : "r"(__float_as_uint(a.x)), "r"(__float_as_uint(a.y)),
          "r"(__float_as_uint(a.z)), "r"(__float_as_uint(a.w)),
          "r"(__float_as_uint(b0)), "r"(__float_as_uint(b1)));
}
__device__ __forceinline__ uint32_t h2pack(float lo, float hi) {
    __half2 h = __halves2half2(__float2half_rn(lo), __float2half_rn(hi));
    return *(uint32_t*)&h;
}
__device__ __forceinline__ void split2(float a, float b, uint32_t& hi, uint32_t& lo) {
    float ha = __half2float(__float2half_rn(a));
    float hb = __half2float(__float2half_rn(b));
    hi = h2pack(a, b);
    lo = h2pack(a - ha, b - hb);
}
#define CP_ASYNC16(dst, src) \
    asm volatile("cp.async.cg.shared.global [%0], [%1], 16;" \
                 :: "r"(dst), "l"(src))
#define CP_COMMIT() asm volatile("cp.async.commit_group;" ::: "memory")
#define CP_WAIT2()  asm volatile("cp.async.wait_group 2;" ::: "memory")
#define CP_WAIT0()  asm volatile("cp.async.wait_group 0;" ::: "memory")

// ============================ prep kernel (merged) ==========================
__global__ void k_prep(const float* __restrict__ emb, const float* __restrict__ b2,
                       const float* __restrict__ w2, float* __restrict__ w2t,
                       const float* __restrict__ dw2, float4* __restrict__ Dp,
                       const float* __restrict__ W1, float4* __restrict__ Wp) {
    int b = blockIdx.x, t = threadIdx.x;
    if (b < 64) {
        g_key[b * 256 + t] = 0xFFFFFFFFFFFFFFFFull;
    } else if (b < 80) {
        int r = (b - 64) * 256 + t;
        const float4* p = (const float4*)(emb + (size_t)r * LL);
        const float4* q = (const float4*)b2;
        float s = 0.f, u = 0.f;
#pragma unroll
        for (int i = 0; i < LL / 4; i++) {
            float4 v = p[i], w = q[i];
            s += v.x * v.x + v.y * v.y + v.z * v.z + v.w * v.w;
            u += v.x * w.x + v.y * w.y + v.z * w.z + v.w * w.w;
        }
        g_c[r] = s - 2.0f * u;
    } else if (b < 144) {
        int idx = (b - 80) * 256 + t;
        int l = idx >> 6, j = idx & 63;
        w2t[l * 64 + j] = w2[j * 256 + l];
    } else if (b < 240) {
        int idx = (b - 144) * 256 + t;
        int np = idx / 384;
        int rem = idx % 384;
        int kt = rem >> 5, lane = rem & 31;
        int n0 = np * 16 + (lane >> 2);
        int kb = kt * 16 + 2 * (lane & 3);
        float4 o;
#pragma unroll
        for (int e = 0; e < 4; e++) {
            int n = n0 + (e >> 1) * 8;
            int kp = kb + (e & 1) * 8;
            int k = (kp < 64) ? kp : (kp < 128 ? kp - 64 : kp - 128);
            bool is_lo = (kp >= 64 && kp < 128);
            float v0 = dw2[(size_t)k * 1024 + n];
            float v1 = dw2[(size_t)(k + 1) * 1024 + n];
            uint32_t h, l;
            split2(v0, v1, h, l);
            ((float*)&o)[e] = __uint_as_float(is_lo ? l : h);
        }
        Dp[idx] = o;
    } else {
        int idx = (b - 240) * 256 + t;
        int g = idx >> 11, ktg = (idx >> 5) & 63, lane = idx & 31;
        int n = g * 8 + (lane >> 2);
        int kb = ktg * 16 + 2 * (lane & 3);
        float4 o;
        uint32_t h0, l0, h1, l1;
        split2(W1[(size_t)kb * 64 + n],       W1[(size_t)(kb + 1) * 64 + n], h0, l0);
        split2(W1[(size_t)(kb + 8) * 64 + n], W1[(size_t)(kb + 9) * 64 + n], h1, l1);
        o.x = __uint_as_float(h0);
        o.y = __uint_as_float(h1);
        o.z = __uint_as_float(l0);
        o.w = __uint_as_float(l1);
        Wp[idx] = o;
    }
}

// ============================ enc1 fp16 tensor-core GEMM ====================
__global__ __launch_bounds__(256) void k_enc1_mma(
    const float* __restrict__ X, const float4* __restrict__ Wp,
    const float* __restrict__ bias, float4* __restrict__ Ap) {
    extern __shared__ char smraw[];
    float* xs = (float*)smraw;                  // 3 x [64][68] floats
    float4* ws = (float4*)(smraw + 52224);      // 3 x 1024 float4
    const uint32_t sb = smem_u32(smraw);
    const int tid = threadIdx.x, warp = tid >> 5, lane = tid & 31;
    const int wm = warp >> 1, wn = warp & 1;
    const int m0 = blockIdx.x * E_BM;
    float acc[4][4] = {};

    auto stage = [&](int c) {
        const int buf = c % 3;
        const uint32_t xb = sb + (uint32_t)buf * 17408u;
        const uint32_t wb = sb + 52224u + (uint32_t)buf * 16384u;
#pragma unroll
        for (int i = 0; i < 4; i++) {
            int s = i * 256 + tid;
            int row = s >> 4, q = s & 15;
            const float* src = X + (size_t)(m0 + row) * 1024 + c * 64 + q * 4;
            CP_ASYNC16(xb + (uint32_t)(row * 272 + q * 16), src);
        }
#pragma unroll
        for (int i = 0; i < 4; i++) {
            int s = i * 256 + tid;
            int g = s >> 7, ktl = (s >> 5) & 3, ln = s & 31;
            const float4* src = Wp + ((size_t)g * 64 + c * 4 + ktl) * 32 + ln;
            CP_ASYNC16(wb + (uint32_t)s * 16u, src);
        }
    };
    stage(0); CP_COMMIT();
    stage(1); CP_COMMIT();

    const int r = lane >> 2, cc = lane & 3;
    for (int c = 0; c < E_NCH; c++) {
        if (c + 2 < E_NCH) stage(c + 2);
        CP_COMMIT();
        CP_WAIT2();
        __syncthreads();
        const float* xc = xs + (c % 3) * 4352;
        const float4* wc = ws + (c % 3) * 1024;
#pragma unroll
        for (int kt = 0; kt < 4; kt++) {
            float4 bw[4];
#pragma unroll
            for (int nf = 0; nf < 4; nf++)
                bw[nf] = wc[(wn * 4 + nf) * 128 + kt * 32 + lane];
            const float* xp = xc + (size_t)(wm * 16) * 68 + kt * 16;
            float2 u0 = *(const float2*)(xp + r * 68 + 2 * cc);
            float2 u1 = *(const float2*)(xp + (r + 8) * 68 + 2 * cc);
            float2 u2 = *(const float2*)(xp + r * 68 + 2 * cc + 8);
            float2 u3 = *(const float2*)(xp + (r + 8) * 68 + 2 * cc + 8);
            float4 ah, al;
            uint32_t h, l;
            split2(u0.x, u0.y, h, l); ah.x = __uint_as_float(h); al.x = __uint_as_float(l);
            split2(u1.x, u1.y, h, l); ah.y = __uint_as_float(h); al.y = __uint_as_float(l);
            split2(u2.x, u2.y, h, l); ah.z = __uint_as_float(h); al.z = __uint_as_float(l);
            split2(u3.x, u3.y, h, l); ah.w = __uint_as_float(h); al.w = __uint_as_float(l);
#pragma unroll
            for (int nf = 0; nf < 4; nf++) {
                mma16(acc[nf], ah, bw[nf].x, bw[nf].y);
                mma16(acc[nf], ah, bw[nf].z, bw[nf].w);
                mma16(acc[nf], al, bw[nf].x, bw[nf].y);
            }
        }
        __syncthreads();
    }
    CP_WAIT0();

    {
        const int mtile = blockIdx.x * 4 + wm;
#pragma unroll
        for (int p = 0; p < 2; p++) {
            const int cb = wn * 32 + p * 16 + 2 * cc;
            float b0 = bias[cb],     b1v = bias[cb + 1];
            float b2 = bias[cb + 8], b3v = bias[cb + 9];
            float v0 = fmaxf(acc[2 * p][0] + b0,  0.f);
            float v1 = fmaxf(acc[2 * p][1] + b1v, 0.f);
            float v2 = fmaxf(acc[2 * p][2] + b0,  0.f);
            float v3 = fmaxf(acc[2 * p][3] + b1v, 0.f);
            float w0 = fmaxf(acc[2 * p + 1][0] + b2,  0.f);
            float w1 = fmaxf(acc[2 * p + 1][1] + b3v, 0.f);
            float w2 = fmaxf(acc[2 * p + 1][2] + b2,  0.f);
            float w3 = fmaxf(acc[2 * p + 1][3] + b3v, 0.f);
            float4 hf, lf;
            uint32_t h, l;
            split2(v0, v1, h, l); hf.x = __uint_as_float(h); lf.x = __uint_as_float(l);
            split2(v2, v3, h, l); hf.y = __uint_as_float(h); lf.y = __uint_as_float(l);
            split2(w0, w1, h, l); hf.z = __uint_as_float(h); lf.z = __uint_as_float(l);
            split2(w2, w3, h, l); hf.w = __uint_as_float(h); lf.w = __uint_as_float(l);
            const int kt = wn * 2 + p;
            Ap[((size_t)mtile * 8 + kt) * 32 + lane]     = hf;
            Ap[((size_t)mtile * 8 + kt + 4) * 32 + lane] = lf;
        }
    }
}

// ============================ dual P/G GEMM + B' emission ===================
__global__ __launch_bounds__(256) void k_dual(
    const float* __restrict__ emb, const float* __restrict__ Wp,
    const float* __restrict__ Wg, const float* __restrict__ bg,
    float* __restrict__ G, float4* __restrict__ Bp) {
    __shared__ float a_s[BK][32 + PAD];
    __shared__ float wp_s[BK][64 + PAD];
    __shared__ float wg_s[BK][64 + PAD];
    __shared__ float s_P[32][68];
    int tid = threadIdx.x;
    int tx = tid & 15, ty = tid >> 4;
    int m0 = blockIdx.x * 32;
    float accp[2][4] = {}, accg[2][4] = {};

    for (int k0 = 0; k0 < LL; k0 += BK) {
        {
            int row = tid >> 3, kq = tid & 7;
            float4 v = *(const float4*)(emb + (size_t)(m0 + row) * LL + k0 + kq * 4);
            a_s[kq * 4 + 0][row] = v.x; a_s[kq * 4 + 1][row] = v.y;
            a_s[kq * 4 + 2][row] = v.z; a_s[kq * 4 + 3][row] = v.w;
        }
#pragma unroll
        for (int i = 0; i < 2; i++) {
            int f4 = tid + i * 256;
            int kr = f4 >> 4, nq = f4 & 15;
            float4 vp = *(const float4*)(Wp + (size_t)(k0 + kr) * 64 + nq * 4);
            wp_s[kr][nq * 4 + 0] = vp.x; wp_s[kr][nq * 4 + 1] = vp.y;
            wp_s[kr][nq * 4 + 2] = vp.z; wp_s[kr][nq * 4 + 3] = vp.w;
            float4 vg = *(const float4*)(Wg + (size_t)(k0 + kr) * 64 + nq * 4);
            wg_s[kr][nq * 4 + 0] = vg.x; wg_s[kr][nq * 4 + 1] = vg.y;
            wg_s[kr][nq * 4 + 2] = vg.z; wg_s[kr][nq * 4 + 3] = vg.w;
        }
        __syncthreads();
#pragma unroll
        for (int k = 0; k < BK; k++) {
            float a0 = a_s[k][ty * 2], a1 = a_s[k][ty * 2 + 1];
            float bp[4], bgv[4];
            *(float4*)bp  = *(float4*)&wp_s[k][tx * 4];
            *(float4*)bgv = *(float4*)&wg_s[k][tx * 4];
#pragma unroll
            for (int j = 0; j < 4; j++) {
                accp[0][j] += a0 * bp[j];  accp[1][j] += a1 * bp[j];
                accg[0][j] += a0 * bgv[j]; accg[1][j] += a1 * bgv[j];
            }
        }
        __syncthreads();
    }
    float4 bv = *(const float4*)(bg + tx * 4);
#pragma unroll
    for (int i = 0; i < 2; i++) {
        int m = m0 + ty * 2 + i;
        float4 vg;
        vg.x = fmaxf(accg[i][0] + bv.x, 0.f);
        vg.y = fmaxf(accg[i][1] + bv.y, 0.f);
        vg.z = fmaxf(accg[i][2] + bv.z, 0.f);
        vg.w = fmaxf(accg[i][3] + bv.w, 0.f);
        *(float4*)(G + (size_t)m * 64 + tx * 4) = vg;
        *(float4*)&s_P[ty * 2 + i][tx * 4] = *(float4*)accp[i];
    }
    __syncthreads();

#pragma unroll
    for (int j = 0; j < 2; j++) {
        int idx = j * 256 + tid;
        int nt = idx >> 8;
        int rem = idx & 255;
        int kt = rem >> 5, lane = rem & 31;
        int nl = nt * 16 + (lane >> 2);
        int kb = (kt & 3) * 16 + 2 * (lane & 3);
        bool is_lo = (kt >= 4);
        float4 o;
#pragma unroll
        for (int e = 0; e < 4; e++) {
            int n = nl + (e >> 1) * 8;
            int k = kb + (e & 1) * 8;
            uint32_t h, l;
            split2(s_P[n][k], s_P[n][k + 1], h, l);
            ((float*)&o)[e] = __uint_as_float(is_lo ? l : h);
        }
        Bp[((size_t)(blockIdx.x * 2 + nt) * 8 + kt) * 32 + lane] = o;
    }
}

// ============================ table fp16 mma GEMM ===========================
__global__ __launch_bounds__(256) void k_table_mma(
    const float* __restrict__ G, const float4* __restrict__ Dp,
    const float* __restrict__ bias, float* __restrict__ T) {
    extern __shared__ char tsm[];
    float* a_s = (float*)tsm;                      // [128][68] fp32 G tile
    float4* bs = (float4*)(tsm + 34816);           // 3072 float4 B' frags
    const uint32_t sb = smem_u32(tsm);
    const int tid = threadIdx.x, warp = tid >> 5, lane = tid & 31;
    const int wm = warp >> 1, wn = warp & 1;
    const int n0 = blockIdx.x * 128, m0 = blockIdx.y * 128;

#pragma unroll
    for (int i = 0; i < 8; i++) {
        int s = i * 256 + tid;
        int row = s >> 4, q = s & 15;
        CP_ASYNC16(sb + (uint32_t)(row * 272 + q * 16),
                   G + (size_t)(m0 + row) * 64 + q * 4);
    }
    const float4* dsrc = Dp + (size_t)(n0 >> 4) * 384;
#pragma unroll
    for (int i = 0; i < 12; i++) {
        int s = i * 256 + tid;
        CP_ASYNC16(sb + 34816u + (uint32_t)s * 16u, dsrc + s);
    }
    CP_COMMIT();
    CP_WAIT0();
    __syncthreads();

    const int r = lane >> 2, cc = lane & 3;
    float acc[2][8][4] = {};
#pragma unroll
    for (int kpos = 0; kpos < 4; kpos++) {
        float4 ah[2], al[2];
#pragma unroll
        for (int mf = 0; mf < 2; mf++) {
            const float* xp = a_s + (size_t)(wm * 32 + mf * 16) * 68 + kpos * 16;
            float2 u0 = *(const float2*)(xp + r * 68 + 2 * cc);
            float2 u1 = *(const float2*)(xp + (r + 8) * 68 + 2 * cc);
            float2 u2 = *(const float2*)(xp + r * 68 + 2 * cc + 8);
            float2 u3 = *(const float2*)(xp + (r + 8) * 68 + 2 * cc + 8);
            uint32_t h, l;
            split2(u0.x, u0.y, h, l); ah[mf].x = __uint_as_float(h); al[mf].x = __uint_as_float(l);
            split2(u1.x, u1.y, h, l); ah[mf].y = __uint_as_float(h); al[mf].y = __uint_as_float(l);
            split2(u2.x, u2.y, h, l); ah[mf].z = __uint_as_float(h); al[mf].z = __uint_as_float(l);
            split2(u3.x, u3.y, h, l); ah[mf].w = __uint_as_float(h); al[mf].w = __uint_as_float(l);
        }
#pragma unroll
        for (int term = 0; term < 3; term++) {
            const int kt = kpos + term * 4;
#pragma unroll
            for (int npl = 0; npl < 4; npl++) {
                float4 bf = bs[((wn * 4 + npl) * KT_TOT + kt) * 32 + lane];
#pragma unroll
                for (int mf = 0; mf < 2; mf++) {
                    const float4& aa = (term == 2) ? al[mf] : ah[mf];
                    mma16(acc[mf][npl * 2],     aa, bf.x, bf.y);
                    mma16(acc[mf][npl * 2 + 1], aa, bf.z, bf.w);
                }
            }
        }
    }

#pragma unroll
    for (int mf = 0; mf < 2; mf++) {
        int row0 = m0 + wm * 32 + mf * 16 + r;
#pragma unroll
        for (int nf = 0; nf < 8; nf++) {
            int n = n0 + wn * 64 + nf * 8 + 2 * cc;
            float b0 = bias[n], b1v = bias[n + 1];
            float2 v0, v1;
            v0.x = acc[mf][nf][0] + b0;  v0.y = acc[mf][nf][1] + b1v;
            v1.x = acc[mf][nf][2] + b0;  v1.y = acc[mf][nf][3] + b1v;
            *(float2*)(T + (size_t)row0 * 1024 + n)       = v0;
            *(float2*)(T + (size_t)(row0 + 8) * 1024 + n) = v1;
        }
    }
}

// ============================ fp16 mma distance kernel ======================
// 128m x 256n per CTA, two 128x128 subtiles reusing A. hi/lo K=64 layout.
// Argmin fold: transient fp32 (bd,bc) per slot per subtile -> 1 pack + 1 atomic.
__global__ __launch_bounds__(256, 2) void k_dist_mma(
    const float4* __restrict__ Ap, const float4* __restrict__ Bp) {
    extern __shared__ float4 sm[];
    __shared__ unsigned long long s_key[128];
    __shared__ float s_c[256];

    const int tid = threadIdx.x;
    const int warp = tid >> 5, lane = tid & 31;
    const int wm = warp >> 2, wn = warp & 3;     // warp tile 64m x 32n
    const int mt0 = blockIdx.y * 8;
    const int m0 = blockIdx.y * 128, n0 = blockIdx.x * 256;

    if (tid < 128) s_key[tid] = 0xFFFFFFFFFFFFFFFFull;
    s_c[tid] = g_c[n0 + tid];

    const uint32_t sb = smem_u32(sm);
    {
        const float4* ga = Ap + (size_t)mt0 * 256;
#pragma unroll
        for (int i = 0; i < 8; i++) {
            int s = i * 256 + tid;
            CP_ASYNC16(sb + (uint32_t)s * 16u, ga + s);
        }
        const float4* gb = Bp + (size_t)blockIdx.x * 4096;
#pragma unroll
        for (int i = 0; i < 16; i++) {
            int s = i * 256 + tid;
            CP_ASYNC16(sb + 32768u + (uint32_t)s * 16u, gb + s);
        }
    }
    CP_COMMIT();
    CP_WAIT0();
    __syncthreads();

    const float4* SA = sm;
#pragma unroll
    for (int j = 0; j < 2; j++) {
        const float4* SB = sm + 2048 + j * 2048;
        float acc[4][4][4] = {};
#pragma unroll
        for (int kt = 0; kt < 4; kt++) {
            float4 bh[2], bl[2];
#pragma unroll
            for (int p = 0; p < 2; p++) {
                bh[p] = SB[((wn * 2 + p) * 8 + kt) * 32 + lane];
                bl[p] = SB[((wn * 2 + p) * 8 + kt + 4) * 32 + lane];
            }
#pragma unroll
            for (int mf = 0; mf < 4; mf++) {
                float4 ah = SA[((wm * 4 + mf) * 8 + kt) * 32 + lane];
                float4 al = SA[((wm * 4 + mf) * 8 + kt + 4) * 32 + lane];
#pragma unroll
                for (int p = 0; p < 2; p++) {
                    mma16(acc[mf][2 * p],     ah, bh[p].x, bh[p].y);
                    mma16(acc[mf][2 * p],     ah, bl[p].x, bl[p].y);
                    mma16(acc[mf][2 * p],     al, bh[p].x, bh[p].y);
                    mma16(acc[mf][2 * p + 1], ah, bh[p].z, bh[p].w);
                    mma16(acc[mf][2 * p + 1], ah, bl[p].z, bl[p].w);
                    mma16(acc[mf][2 * p + 1], al, bh[p].z, bh[p].w);
                }
            }
        }
        // fold subtile j: transient fp32 min per (mf, half) slot, then 1 atomic.
        // ascending columns + strict '<' preserves first-index tie-break; cross-
        // subtile/CTA resolution via u64 key (idx in low bits) atomicMin.
#pragma unroll
        for (int mf = 0; mf < 4; mf++) {
#pragma unroll
            for (int half = 0; half < 2; half++) {
                float bd = __int_as_float(0x7f800000);
                int bc = 0;
#pragma unroll
                for (int nt = 0; nt < 4; nt++) {
                    int cb = wn * 32 + nt * 8 + 2 * (lane & 3);
                    float d0 = fmaf(-2.0f, acc[mf][nt][half * 2 + 0],
                                    s_c[j * 128 + cb]);
                    float d1 = fmaf(-2.0f, acc[mf][nt][half * 2 + 1],
                                    s_c[j * 128 + cb + 1]);
                    if (d0 < bd) { bd = d0; bc = cb; }
                    if (d1 < bd) { bd = d1; bc = cb + 1; }
                }
                int rloc = wm * 64 + mf * 16 + (lane >> 2) + half * 8;
                unsigned long long key =
                    ((unsigned long long)f2s(bd) << 32) |
                    (unsigned int)(n0 + j * 128 + bc);
                atomicMin(&s_key[rloc], key);
            }
        }
    }
    __syncthreads();
    if (tid < 128) atomicMin(&g_key[m0 + tid], s_key[tid]);
}

// ---------------------------------------------------------------------------
__global__ void k_gather(float* __restrict__ out) {
    int b = blockIdx.x * 2 + (threadIdx.x >> 8);
    int q = threadIdx.x & 255;
    unsigned int idx = (unsigned int)(g_key[b] & 0xFFFFFFFFu);
    const float4* src = (const float4*)(g_table + (size_t)idx * SS);
    float4 v = src[q];
    float4* dst = (float4*)(out + (size_t)b * SS) + q;
    asm volatile("st.global.cs.v4.f32 [%0], {%1, %2, %3, %4};"
                 :: "l"(dst), "f"(v.x), "f"(v.y), "f"(v.z), "f"(v.w));
}

// ---------------------------------------------------------------------------
extern "C" void kernel_launch(void* const* d_in, const int* in_sizes, int n_in,
                              void* d_out, int out_size) {
    const float* x    = (const float*)d_in[0];
    const float* ew1  = (const float*)d_in[1];
    const float* eb1  = (const float*)d_in[2];
    const float* ew2  = (const float*)d_in[3];
    const float* eb2  = (const float*)d_in[4];
    const float* emb  = (const float*)d_in[5];
    const float* dw1  = (const float*)d_in[6];
    const float* db1  = (const float*)d_in[7];
    const float* dw2  = (const float*)d_in[8];
    const float* db2  = (const float*)d_in[9];
    float* out = (float*)d_out;

    void *p_w2t, *p_w1p, *p_dw2p, *p_ap, *p_bp, *p_G, *p_table;
    cudaGetSymbolAddress(&p_w2t, g_w2t);
    cudaGetSymbolAddress(&p_w1p, g_w1p);
    cudaGetSymbolAddress(&p_dw2p, g_dw2p);
    cudaGetSymbolAddress(&p_ap, g_ap);
    cudaGetSymbolAddress(&p_bp, g_bp);
    cudaGetSymbolAddress(&p_G, g_G);
    cudaGetSymbolAddress(&p_table, g_table);

    static int smem_set = 0;
    const int DYN_DIST = 98304;
    const int DYN_ENC1 = 101376;
    const int DYN_TAB  = 34816 + 3072 * 16;
    if (!smem_set) {
        cudaFuncSetAttribute(k_dist_mma, cudaFuncAttributeMaxDynamicSharedMemorySize,
                             DYN_DIST);
        cudaFuncSetAttribute(k_enc1_mma, cudaFuncAttributeMaxDynamicSharedMemorySize,
                             DYN_ENC1);
        cudaFuncSetAttribute(k_table_mma, cudaFuncAttributeMaxDynamicSharedMemorySize,
                             DYN_TAB);
        smem_set = 1;
    }

    // 1. prep
    k_prep<<<304, 256>>>(emb, eb2, ew2, (float*)p_w2t, dw2, (float4*)p_dw2p,
                         ew1, (float4*)p_w1p);
    // 2. P/G fused; hi/lo B' frags
    k_dual<<<KK / 32, 256>>>(emb, (const float*)p_w2t, dw1, db1,
                             (float*)p_G, (float4*)p_bp);
    // 3. encoder layer 1 -> hi/lo A' frags
    k_enc1_mma<<<MB / E_BM, 256, DYN_ENC1>>>(x, (const float4*)p_w1p, eb1,
                                             (float4*)p_ap);
    // 4. distances + fused argmin (profiled slot)
    k_dist_mma<<<dim3(KK / 256, MB / 128), 256, DYN_DIST>>>((const float4*)p_ap,
                                                            (const float4*)p_bp);
    // 5. decoder table
    k_table_mma<<<dim3(SS / 128, KK / 128), 256, DYN_TAB>>>(
        (const float*)p_G, (const float4*)p_dw2p, db2, (float*)p_table);
    // 6. decoded output gather
    k_gather<<<MB / 2, 512>>>(out);
}